// round 16
// baseline (speedup 1.0000x reference)
#include <cuda_runtime.h>

#define BATCH   2
#define CF      64
#define NXD     468
#define NYD     468
#define GRID    (NXD * NYD)      // 219024
#define NP_PER  60000
#define HRD     48
#define WRD     512
#define RSP     (HRD * WRD)      // 24576
#define TCELL   64               // cells per gather tile (last tile has 16)
#define NTILES  ((GRID + TCELL - 1) / TCELL)   // 3423

// Winner-index maps: [0 .. B*G) spatial, [B*G .. 2*B*G) bev. -1 = empty.
__device__ __align__(16) int g_win[2 * BATCH * GRID];
// Channel-last transposed range_out: [B][RSP][64]
__device__ __align__(16) float g_rot[BATCH * RSP * CF];

#define SCAT_BLOCKS 157          // ceil(40000 threads / 256), 4 points/thread
#define TRANS_BLOCKS (RSP / 128 * (CF / 32) * BATCH)   // 768

// Fused prologue: blocks [0,157) scatter winners (4 points per thread, all
// loads issued up-front for MLP); rest transpose range_out (vectorized).
// Last-write-wins == highest point index (serial XLA scatter order).
// XLA's arcp rewrite makes v/0.16f == v*6.25f exactly (verified rel_err==0.0).
__global__ void __launch_bounds__(256) k_prologue(
        const int* __restrict__ vc, const float* __restrict__ lp,
        const float* __restrict__ ro, int n_pillar, int n_laser) {
    if (blockIdx.x < SCAT_BLOCKS) {
        int j = blockIdx.x * 256 + threadIdx.x;
        int n_p4 = (n_pillar + 3) >> 2;        // 10000
        if (j < n_p4) {
            // 4 pillar points: 4 independent LDG.128 of voxel_coords rows.
            int p0 = j * 4;
            int4 c[4];
            #pragma unroll
            for (int k = 0; k < 4; k++)
                c[k] = (p0 + k < n_pillar) ? ((const int4*)vc)[p0 + k]
                                           : make_int4(-1, 0, 0, 0);
            #pragma unroll
            for (int k = 0; k < 4; k++) {
                int b   = c[k].x;
                int lin = c[k].y + c[k].z * NXD + c[k].w;
                if (b >= 0 && b < BATCH && lin >= 0 && lin < GRID)
                    atomicMax(&g_win[b * GRID + lin], p0 + k);
            }
        } else {
            int p0 = (j - n_p4) * 4;
            if (p0 >= n_laser) return;
            // 8 independent scalar loads up front.
            float xx[4], yy[4];
            #pragma unroll
            for (int k = 0; k < 4; k++) {
                int p = min(p0 + k, n_laser - 1);
                xx[k] = lp[p * 5 + 1];
                yy[k] = lp[p * 5 + 2];
            }
            #pragma unroll
            for (int k = 0; k < 4; k++) {
                int p = p0 + k;
                if (p >= n_laser) break;
                float x = xx[k], y = yy[k];
                bool valid = (x > 0.0f) && (x < 69.12f)
                          && (y > -39.68f) && (y < 39.68f)
                          && (x >= 0.0f) && (x < 468.0f)
                          && (y >= 0.0f) && (y < 468.0f);
                if (!valid) continue;
                int xi = (int)__fmul_rn(-y, 6.25f) + 248;   // XOFF
                int yi = (int)__fmul_rn(-x, 6.25f) + 432;   // YOFF
                xi = min(max(xi, 0), 495);
                yi = min(max(yi, 0), 431);
                if (xi >= NXD) continue;                    // mode='drop'
                int b = p / NP_PER;
                atomicMax(&g_win[BATCH * GRID + b * GRID + yi * NXD + xi], p);
            }
        }
    } else {
        // Vectorized transpose: ro (B,64,RSP) -> g_rot (B,RSP,64).
        // Tile = 32 channels x 128 pixels. LDG.128 in, STG.128 out.
        __shared__ float tl[32][129];
        int j  = blockIdx.x - SCAT_BLOCKS;     // 0..767
        int sI = j % (RSP / 128);              // 0..191
        int cI = (j / (RSP / 128)) & 1;        // channel chunk
        int b  = j / (RSP / 128 * 2);
        int s0 = sI * 128;
        int c0 = cI * 32;
        int t  = threadIdx.x;
        int q  = t & 31;
        #pragma unroll
        for (int k = 0; k < 4; k++) {
            int c = k * 8 + (t >> 5);
            float4 d = *(const float4*)&ro[(size_t)(b * CF + c0 + c) * RSP
                                           + s0 + q * 4];
            tl[c][0 * 32 + q] = d.x;
            tl[c][1 * 32 + q] = d.y;
            tl[c][2 * 32 + q] = d.z;
            tl[c][3 * 32 + q] = d.w;
        }
        __syncthreads();
        int v = t & 7;
        #pragma unroll
        for (int it = 0; it < 4; it++) {
            int p   = 4 * (t >> 3) + it;
            int phi = it * 32 + (t >> 3);
            float4 o;
            o.x = tl[4 * v + 0][phi];
            o.y = tl[4 * v + 1][phi];
            o.z = tl[4 * v + 2][phi];
            o.w = tl[4 * v + 3][phi];
            *(float4*)&g_rot[(size_t)(b * RSP + s0 + p) * CF + c0 + v * 4] = o;
        }
    }
}

// R14 gather (46.3 us) with 32-bit address arithmetic (all offsets < 2^27
// elements, so unsigned math replaces IMAD.WIDE chains). Memory pattern
// unchanged: full-row coalesced loads (16 lanes per winner row, 4 lines per
// warp-LDG), XOR swizzle col = cell ^ 2v (conflict-free STS), store phase
// LDS.128 + STG.128 with branchless half-swap.
__global__ void __launch_bounds__(256, 8) k_gather(
        const float* __restrict__ pf,
        const int*   __restrict__ lx,
        const int*   __restrict__ ly,
        const float* __restrict__ lp,
        float*       __restrict__ out) {
    __shared__ float s_val[64][64];        // 16 KB: [ch_local][swizzled cell]
    __shared__ float s_zc[TCELL];
    __shared__ int   s_off[TCELL];
    __shared__ int   s_wiS[TCELL];

    int tile = blockIdx.x;
    int b    = blockIdx.y;
    int t    = threadIdx.x;
    int cell0  = tile * TCELL;
    int ncells = min(TCELL, GRID - cell0);

    if (t < TCELL) {
        int wiS = -1, wiB = -1;
        if (t < ncells) {
            wiS = g_win[b * GRID + cell0 + t];
            wiB = g_win[BATCH * GRID + b * GRID + cell0 + t];
        }
        s_wiS[t] = wiS;
        float zc = 0.0f; int off = -1;
        if (wiB >= 0) {
            float z = lp[wiB * 5 + 3];
            zc  = fminf(fmaxf(z, -2.0f), 4.0f);
            off = b * RSP + ly[wiB * 2 + 1] * WRD + lx[wiB * 2 + 1];
        }
        s_zc[t] = zc; s_off[t] = off;
    }
    __syncthreads();

    int crel = t >> 4;                     // 0..15: cell within pass group
    int v    = t & 15;                     // quad 0..15 = full row coverage
    float* op = out + (unsigned)(b * 128 * GRID + cell0);

    float4 d[4];
    // ---- Chunk A (spatial): load 4 passes, full-row coalesced ----
    #pragma unroll
    for (int p = 0; p < 4; p++) {
        int cell = p * 16 + crel;
        int wi = s_wiS[cell];
        d[p] = make_float4(0.f, 0.f, 0.f, 0.f);
        if (wi >= 0)
            d[p] = *(const float4*)(pf + ((unsigned)wi << 6) + (v << 2));
    }
    // STS chunk A (swizzled, conflict-free).
    #pragma unroll
    for (int p = 0; p < 4; p++) {
        int cell = p * 16 + crel;
        int col  = (cell ^ (2 * v)) & 63;
        float va[4] = {d[p].x, d[p].y, d[p].z, d[p].w};
        #pragma unroll
        for (int k = 0; k < 4; k++) s_val[v * 4 + k][col] = va[k];
    }
    // ---- Prefetch chunk B (bev) into regs; hides under A's store phase ----
    #pragma unroll
    for (int p = 0; p < 4; p++) {
        int cell = p * 16 + crel;
        int off  = s_off[cell];
        float4 r = make_float4(0.f, 0.f, 0.f, 0.f);
        if (off >= 0) {
            float zc = s_zc[cell];
            r = *(const float4*)(g_rot + ((unsigned)off << 6) + (v << 2));
            r.x = __fmul_rn(zc, r.x); r.y = __fmul_rn(zc, r.y);
            r.z = __fmul_rn(zc, r.z); r.w = __fmul_rn(zc, r.w);
        }
        d[p] = r;
    }
    __syncthreads();
    // ---- Store chunk A: LDS.128 + STG.128, coalesced 256B per 16 lanes ----
    #pragma unroll
    for (int it = 0; it < 4; it++) {
        int s  = t + it * 256;
        int cl = s >> 4;                   // channel 0..63
        int cv = s & 15;                   // cell quad
        if (cv * 4 < ncells) {
            int G = cv ^ (cl >> 3);
            float4 o = *(const float4*)&s_val[cl][G * 4];
            if ((cl >> 2) & 1) o = make_float4(o.z, o.w, o.x, o.y);
            __stcs((float4*)(op + (unsigned)(cl * GRID) + (cv << 2)), o);
        }
    }
    __syncthreads();
    // ---- STS chunk B ----
    #pragma unroll
    for (int p = 0; p < 4; p++) {
        int cell = p * 16 + crel;
        int col  = (cell ^ (2 * v)) & 63;
        float vr[4] = {d[p].x, d[p].y, d[p].z, d[p].w};
        #pragma unroll
        for (int k = 0; k < 4; k++) s_val[v * 4 + k][col] = vr[k];
    }
    __syncthreads();
    // ---- Store chunk B (channels 64..127) ----
    float* opB = op + (unsigned)(CF * GRID);
    #pragma unroll
    for (int it = 0; it < 4; it++) {
        int s  = t + it * 256;
        int cl = s >> 4;
        int cv = s & 15;
        if (cv * 4 < ncells) {
            int G = cv ^ (cl >> 3);
            float4 o = *(const float4*)&s_val[cl][G * 4];
            if ((cl >> 2) & 1) o = make_float4(o.z, o.w, o.x, o.y);
            __stcs((float4*)(opB + (unsigned)(cl * GRID) + (cv << 2)), o);
        }
    }
}

extern "C" void kernel_launch(void* const* d_in, const int* in_sizes, int n_in,
                              void* d_out, int out_size) {
    const float* pf = (const float*)d_in[0];   // pillar_features (B*P_PER, 64)
    const int*   vc = (const int*)  d_in[1];   // voxel_coords    (B*P_PER, 4)
    const float* ro = (const float*)d_in[2];   // range_out       (B, 64, 48, 512)
    const int*   lx = (const int*)  d_in[3];   // laser_x         (B*NP, 2)
    const int*   ly = (const int*)  d_in[4];   // laser_y         (B*NP, 2)
    const float* lp = (const float*)d_in[5];   // laser_points    (B*NP, 5)
    float* out = (float*)d_out;

    int n_pillar = in_sizes[1] / 4;
    int n_laser  = in_sizes[5] / 5;

    void* winp = nullptr;
    cudaGetSymbolAddress(&winp, g_win);
    cudaMemsetAsync(winp, 0xFF, sizeof(int) * 2 * BATCH * GRID, 0);  // all -1

    k_prologue<<<SCAT_BLOCKS + TRANS_BLOCKS, 256>>>(vc, lp, ro, n_pillar, n_laser);

    dim3 gg(NTILES, BATCH);                    // (3423, 2)
    k_gather<<<gg, 256>>>(pf, lx, ly, lp, out);
}